// round 13
// baseline (speedup 1.0000x reference)
#include <cuda_runtime.h>
#include <cuda_fp16.h>
#include <cstdint>

#define D_FEAT    128
#define MAX_NODES 65536
#define MAX_EDGES 1100000
#define BIN_CAP   96        // slots per node; Poisson(16) max-degree << 96

// ---------------- static device scratch (allocation-free) -------------------
__device__ int  g_cursor[MAX_NODES];
__device__ int2 g_slots[MAX_NODES * BIN_CAP];   // {src, float_as_int(val)}
__device__ int  g_over_cnt;
__device__ int  g_over_edges[MAX_EDGES];
__device__ __align__(16) __half g_feat16[MAX_NODES * D_FEAT];   // 16.8 MB

// ---------------------------------------------------------------------------
// 1) zero cursors (int4 stores) + overflow counter — tiny, must precede fill
// ---------------------------------------------------------------------------
__global__ void zero_kernel(int n_rows) {
    int i = blockIdx.x * blockDim.x + threadIdx.x;
    int i4 = i * 4;
    if (i4 < n_rows)
        *reinterpret_cast<int4*>(g_cursor + i4) = make_int4(0, 0, 0, 0);
    if (i == 0) g_over_cnt = 0;
}

// ---------------------------------------------------------------------------
// 2) FUSED fill + convert with INTERLEAVED block roles.
//    Edge blocks (atomic-latency bound) and convert blocks (BW bound) are
//    striped proportionally across the block index space, so every wave on
//    every SM co-hosts both kinds — combined time ~ max, not partial-sum.
//    Role assignment: block b is an edge block iff floor((b+1)*eb/nb) >
//    floor(b*eb/nb); exactly eb edge blocks and nb-eb convert blocks.
// ---------------------------------------------------------------------------
__global__ void fill_convert_kernel(const int*    __restrict__ src,
                                    const int*    __restrict__ dst,
                                    const float*  __restrict__ vals,
                                    const float4* __restrict__ feat4,
                                    int n_edges, int total4,
                                    int eb, int nb)
{
    int b = blockIdx.x;
    long long eprev = ((long long)b * eb) / nb;
    bool is_edge = (((long long)(b + 1) * eb) / nb) > eprev;

    if (is_edge) {
        int i = (int)eprev * blockDim.x + threadIdx.x;
        if (i < n_edges) {
            int d   = __ldg(&dst[i]);
            int s   = __ldg(&src[i]);
            float v = __ldg(&vals[i]);
            int pos = atomicAdd(&g_cursor[d], 1);
            if (pos < BIN_CAP)
                g_slots[d * BIN_CAP + pos] = make_int2(s, __float_as_int(v));
            else
                g_over_edges[atomicAdd(&g_over_cnt, 1)] = i;
        }
    } else {
        int cblk = b - (int)eprev;        // 0 .. (nb-eb-1), monotone
        int c = cblk * blockDim.x + threadIdx.x;
        if (c < total4) {
            float4 f = __ldg(&feat4[c]);
            __half2 lo = __floats2half2_rn(f.x, f.y);
            __half2 hi = __floats2half2_rn(f.z, f.w);
            uint2 packed;
            packed.x = *reinterpret_cast<uint32_t*>(&lo);
            packed.y = *reinterpret_cast<uint32_t*>(&hi);
            reinterpret_cast<uint2*>(g_feat16)[c] = packed;
        }
    }
}

// ---------------------------------------------------------------------------
// helper: accumulate v * feat16_row[lane] into acc (4 halves -> 4 fp32 fmas)
// ---------------------------------------------------------------------------
__device__ __forceinline__ void acc_edge(float4& acc, uint2 hp, float v) {
    __half2 h0 = *reinterpret_cast<__half2*>(&hp.x);
    __half2 h1 = *reinterpret_cast<__half2*>(&hp.y);
    float2 a = __half22float2(h0);
    float2 b = __half22float2(h1);
    acc.x = fmaf(v, a.x, acc.x);
    acc.y = fmaf(v, a.y, acc.y);
    acc.z = fmaf(v, b.x, acc.z);
    acc.w = fmaf(v, b.y, acc.w);
}

// ---------------------------------------------------------------------------
// 3) warp-per-node gather (proven R12): lane-parallel slot fetch + shfl
//    distribution -> feature loads pipeline with no memory dependency.
//    READ-ONLY on scratch, NO fences (proven constraints).
// ---------------------------------------------------------------------------
__global__ void gather_kernel(const float4* __restrict__ bias4,
                              float4* __restrict__ out4,
                              const int*   __restrict__ src,
                              const int*   __restrict__ dst,
                              const float* __restrict__ vals,
                              int n_rows)
{
    int gtid = blockIdx.x * blockDim.x + threadIdx.x;
    int node = gtid >> 5;
    int lane = gtid & 31;
    if (node >= n_rows) return;

    const uint2* f16 = reinterpret_cast<const uint2*>(g_feat16);

    float4 acc = __ldg(&bias4[lane]);

    int cnt = g_cursor[node];
    cnt = min(cnt, BIN_CAP);
    const int2* bin = g_slots + (size_t)node * BIN_CAP;

    int2 myslot = make_int2(0, 0);
    if (lane < cnt) myslot = __ldg(&bin[lane]);

    int n0 = min(cnt, 32);
    int e = 0;
    for (; e + 3 < n0; e += 4) {
        int   s0 = __shfl_sync(0xffffffffu, myslot.x, e);
        int   s1 = __shfl_sync(0xffffffffu, myslot.x, e + 1);
        int   s2 = __shfl_sync(0xffffffffu, myslot.x, e + 2);
        int   s3 = __shfl_sync(0xffffffffu, myslot.x, e + 3);
        float v0 = __int_as_float(__shfl_sync(0xffffffffu, myslot.y, e));
        float v1 = __int_as_float(__shfl_sync(0xffffffffu, myslot.y, e + 1));
        float v2 = __int_as_float(__shfl_sync(0xffffffffu, myslot.y, e + 2));
        float v3 = __int_as_float(__shfl_sync(0xffffffffu, myslot.y, e + 3));
        uint2 h0 = __ldg(&f16[(size_t)s0 * 32 + lane]);
        uint2 h1 = __ldg(&f16[(size_t)s1 * 32 + lane]);
        uint2 h2 = __ldg(&f16[(size_t)s2 * 32 + lane]);
        uint2 h3 = __ldg(&f16[(size_t)s3 * 32 + lane]);
        acc_edge(acc, h0, v0);
        acc_edge(acc, h1, v1);
        acc_edge(acc, h2, v2);
        acc_edge(acc, h3, v3);
    }
    for (; e < n0; ++e) {
        int   s = __shfl_sync(0xffffffffu, myslot.x, e);
        float v = __int_as_float(__shfl_sync(0xffffffffu, myslot.y, e));
        uint2 h = __ldg(&f16[(size_t)s * 32 + lane]);
        acc_edge(acc, h, v);
    }
    // rare tail: degree > 32 (P ~ 2e-4 per node)
    for (; e < cnt; ++e) {
        int2 sv = __ldg(&bin[e]);
        uint2 h = __ldg(&f16[(size_t)sv.x * 32 + lane]);
        acc_edge(acc, h, __int_as_float(sv.y));
    }

    // overflow drain (0 in practice: P(deg>96) ~ 1e-40 for this dataset)
    int oc = g_over_cnt;
    if (oc != 0) {
        for (int i = 0; i < oc; ++i) {
            int eid = g_over_edges[i];
            if (__ldg(&dst[eid]) == node) {
                int s   = __ldg(&src[eid]);
                float v = __ldg(&vals[eid]);
                uint2 h = __ldg(&f16[(size_t)s * 32 + lane]);
                acc_edge(acc, h, v);
            }
        }
    }

    out4[(size_t)node * 32 + lane] = acc;
}

// ---------------------------------------------------------------------------
// Fallback (R1 proven path, full fp32) for shapes exceeding static scratch
// ---------------------------------------------------------------------------
__global__ void init_bias_kernel(float4* __restrict__ out,
                                 const float4* __restrict__ bias4,
                                 int total_vec4) {
    int idx = blockIdx.x * blockDim.x + threadIdx.x;
    if (idx >= total_vec4) return;
    out[idx] = __ldg(&bias4[idx & 31]);
}

__global__ void spmm_edge_kernel(const int* __restrict__ src,
                                 const int* __restrict__ dst,
                                 const float* __restrict__ vals,
                                 const float* __restrict__ feat,
                                 float* __restrict__ out,
                                 int n_edges) {
    int gtid = blockIdx.x * blockDim.x + threadIdx.x;
    int edge = gtid >> 5;
    int lane = gtid & 31;
    if (edge >= n_edges) return;

    int s = 0, d = 0;
    float v = 0.0f;
    if (lane == 0) { s = src[edge]; d = dst[edge]; v = vals[edge]; }
    s = __shfl_sync(0xffffffffu, s, 0);
    d = __shfl_sync(0xffffffffu, d, 0);
    v = __shfl_sync(0xffffffffu, v, 0);

    const float4* frow = reinterpret_cast<const float4*>(feat + (size_t)s * D_FEAT);
    float4 f = __ldg(&frow[lane]);
    float4 m = make_float4(f.x * v, f.y * v, f.z * v, f.w * v);

    float* orow = out + (size_t)d * D_FEAT + lane * 4;
    asm volatile("red.global.add.v4.f32 [%0], {%1, %2, %3, %4};"
                 :: "l"(orow), "f"(m.x), "f"(m.y), "f"(m.z), "f"(m.w)
                 : "memory");
}

// ---------------------------------------------------------------------------
// Launch.  d_in[0]=edge_index(2E i32: src then dst)  d_in[1]=edge_vals(E f32)
//          d_in[2]=features(N*128 f32)               d_in[3]=bias(128 f32)
// ---------------------------------------------------------------------------
extern "C" void kernel_launch(void* const* d_in, const int* in_sizes, int n_in,
                              void* d_out, int out_size)
{
    const int*   edge_index = (const int*)d_in[0];
    const float* edge_vals  = (const float*)d_in[1];
    const float* features   = (const float*)d_in[2];
    const float* bias       = (const float*)d_in[3];
    float*       out        = (float*)d_out;

    int n_edges = in_sizes[1];
    int n_rows  = in_sizes[2] / D_FEAT;

    const int* src = edge_index;
    const int* dst = edge_index + n_edges;

    if (n_rows <= MAX_NODES && n_edges <= MAX_EDGES) {
        {   // 1) zero cursors (tiny; must precede fill's atomics)
            int work = (n_rows + 3) / 4;
            int th = 256, bl = (work + th - 1) / th;
            zero_kernel<<<bl, th>>>(n_rows);
        }
        {   // 2) fused fill + fp16 convert, interleaved block roles
            int th = 256;
            int total4 = n_rows * (D_FEAT / 4);
            int eb = (n_edges + th - 1) / th;       // edge blocks
            int cb = (total4 + th - 1) / th;        // convert blocks
            int nb = eb + cb;
            fill_convert_kernel<<<nb, th>>>(src, dst, edge_vals,
                                            (const float4*)features,
                                            n_edges, total4, eb, nb);
        }
        {   // 3) gather (warp per node), shfl-distributed slots
            int th = 256;
            long long total = (long long)n_rows * 32;
            int bl = (int)((total + th - 1) / th);
            gather_kernel<<<bl, th>>>((const float4*)bias,
                                      (float4*)out,
                                      src, dst, edge_vals, n_rows);
        }
    } else {
        {   // fallback: bias init + atomic scatter (full fp32)
            int total_vec4 = n_rows * (D_FEAT / 4);
            int th = 256, bl = (total_vec4 + th - 1) / th;
            init_bias_kernel<<<bl, th>>>((float4*)out, (const float4*)bias,
                                         total_vec4);
        }
        {
            int th = 256;
            long long total = (long long)n_edges * 32;
            int bl = (int)((total + th - 1) / th);
            spmm_edge_kernel<<<bl, th>>>(src, dst, edge_vals, features, out,
                                         n_edges);
        }
    }
}